// round 16
// baseline (speedup 1.0000x reference)
#include <cuda_runtime.h>
#include <cstdint>
#include <float.h>

#define BB 4
#define NN 40960
#define KK 16
#define DD 64
#define HH 32
#define NPTS (BB * NN)
#define EPSV 1e-5f
#define PPW 16   // points per warp in pass2

typedef unsigned long long ull;
typedef unsigned int u32;

// ---------- packed f32x2 helpers ----------
__device__ __forceinline__ ull ffma2(ull a, ull b, ull c) {
    ull d;
    asm("fma.rn.f32x2 %0, %1, %2, %3;" : "=l"(d) : "l"(a), "l"(b), "l"(c));
    return d;
}
__device__ __forceinline__ ull pack2(float lo, float hi) {
    ull d;
    asm("mov.b64 %0, {%1, %2};" : "=l"(d) : "f"(lo), "f"(hi));
    return d;
}
__device__ __forceinline__ void unpack2(ull v, float& lo, float& hi) {
    asm("mov.b64 {%0, %1}, %2;" : "=f"(lo), "=f"(hi) : "l"(v));
}
__device__ __forceinline__ u32 cvt_tf32(float f) {
    u32 r;
    asm("cvt.rna.tf32.f32 %0, %1;" : "=r"(r) : "f"(f));
    return r;
}
__device__ __forceinline__ void mma_tf32(float& c0, float& c1, float& c2, float& c3,
                                         u32 a0, u32 a1, u32 a2, u32 a3, u32 b0, u32 b1) {
    asm("mma.sync.aligned.m16n8k8.row.col.f32.tf32.tf32.f32 "
        "{%0,%1,%2,%3}, {%4,%5,%6,%7}, {%8,%9}, {%0,%1,%2,%3};"
        : "+f"(c0), "+f"(c1), "+f"(c2), "+f"(c3)
        : "r"(a0), "r"(a1), "r"(a2), "r"(a3), "r"(b0), "r"(b1));
}
__device__ __forceinline__ u32 smem_u32(const void* p) {
    return (u32)__cvta_generic_to_shared(p);
}

// ---------- folded weights ----------
__device__ ull dW2P[DD][HH / 2];        // [c][hp]  (pass1)
__device__ ull dW3AP[HH][HH / 2];       // W3[:, 0:32] (pass1)
__device__ u32 dW3Btf[HH * HH];         // [h][c] tf32  (pass2 B frags)
__device__ ull dW4BP[HH][HH];           // [c][dp] packed: W4[:,32:64] (pass1 E matvec)
__device__ u32 dW4Atf[DD * HH];         // [d][c] tf32: W4[:,0:32]    (pass2 epilogue)
__device__ float4 dCoefA[HH];           // (m1x, m1y, m1z, w1d) per channel
__device__ float4 dCoefB[HH];           // (m0x, m0y, m0z, b1)  per channel
__device__ float dB2[HH], dB3[HH], dB4[DD];
__device__ int dIdx64;

// ---------- scratch ----------
__device__ float dE[NPTS * DD];     // E = W4b@f + b4 per point (row-major 64)
__device__ float dG[NPTS * HH];     // G = s3*(W3a@f)+b3, PERMUTED for fragment loads
__device__ float dFC[NPTS * HH];    // fc scratch (pass2 warp-private write->read)
__device__ float4 dXYZ4[NPTS];      // (x, y, z, 0)
__device__ int dIdx32buf[NPTS * KK];// neigh_idx narrowed to int32

// ================== prep ==================
__global__ void prep_kernel(const float* __restrict__ W1, const float* __restrict__ W2,
                            const float* __restrict__ W3, const float* __restrict__ W4,
                            const float* __restrict__ g1, const float* __restrict__ b1,
                            const float* __restrict__ g2, const float* __restrict__ b2,
                            const float* __restrict__ g3, const float* __restrict__ b3,
                            const float* __restrict__ g4, const float* __restrict__ b4) {
    int t = threadIdx.x;
    float inv = rsqrtf(1.0f + EPSV);
    for (int i = t; i < DD * (HH / 2); i += blockDim.x) {
        int c = i >> 4, hp = i & 15;
        dW2P[c][hp] = pack2(g2[2 * hp] * inv * W2[(2 * hp) * DD + c],
                            g2[2 * hp + 1] * inv * W2[(2 * hp + 1) * DD + c]);
    }
    for (int i = t; i < HH * (HH / 2); i += blockDim.x) {
        int c = i >> 4, hp = i & 15;
        float s0 = g3[2 * hp] * inv, s1 = g3[2 * hp + 1] * inv;
        dW3AP[c][hp] = pack2(s0 * W3[(2 * hp) * (2 * HH) + c],
                             s1 * W3[(2 * hp + 1) * (2 * HH) + c]);
    }
    for (int i = t; i < HH * HH; i += blockDim.x) {
        int h = i >> 5, c = i & 31;
        dW3Btf[h * HH + c] = cvt_tf32(g3[h] * inv * W3[h * (2 * HH) + HH + c]);
    }
    for (int i = t; i < HH * HH; i += blockDim.x) {
        int c = i >> 5, dp = i & 31;
        dW4BP[c][dp] = pack2(g4[2 * dp] * inv * W4[(2 * dp) * (2 * HH) + HH + c],
                             g4[2 * dp + 1] * inv * W4[(2 * dp + 1) * (2 * HH) + HH + c]);
    }
    for (int i = t; i < DD * HH; i += blockDim.x) {
        int d = i >> 5, c = i & 31;
        dW4Atf[d * HH + c] = cvt_tf32(g4[d] * inv * W4[d * (2 * HH) + c]);
    }
    for (int c = t; c < HH; c += blockDim.x) {
        float s = g1[c] * inv;
        dCoefA[c] = make_float4(s * (W1[c * 10 + 7] - W1[c * 10 + 1]),
                                s * (W1[c * 10 + 8] - W1[c * 10 + 2]),
                                s * (W1[c * 10 + 9] - W1[c * 10 + 3]),
                                s * W1[c * 10 + 0]);
        dCoefB[c] = make_float4(s * (W1[c * 10 + 1] + W1[c * 10 + 4]),
                                s * (W1[c * 10 + 2] + W1[c * 10 + 5]),
                                s * (W1[c * 10 + 3] + W1[c * 10 + 6]),
                                b1[c]);
        dB2[c] = b2[c];
        dB3[c] = b3[c];
    }
    for (int d = t; d < DD; d += blockDim.x) dB4[d] = b4[d];
}

// ================== detect int64 vs int32 neigh_idx ==================
__global__ void detect_kernel(const unsigned int* __restrict__ w) {
    __shared__ int sBad;
    if (threadIdx.x == 0) sBad = 0;
    __syncthreads();
    unsigned int acc = 0;
    for (int i = threadIdx.x; i < 2048; i += blockDim.x) acc |= w[2 * i + 1];
    if (acc) atomicOr(&sBad, 1);
    __syncthreads();
    if (threadIdx.x == 0) dIdx64 = (sBad == 0) ? 1 : 0;
}

// ================== narrow neigh_idx to int32 ==================
__global__ void convert_kernel(const unsigned int* __restrict__ idxw) {
    int i = blockIdx.x * 256 + threadIdx.x;
    dIdx32buf[i] = (int)idxw[(size_t)i << dIdx64];
}

// ================== pass 1: per-point f, G (permuted), E = W4b@f + b4, xyz4 ==================
__global__ void __launch_bounds__(128) pass1_kernel(const float* __restrict__ feat,
                                                    const float* __restrict__ xyz) {
    __shared__ ull sW2[DD][HH / 2];      // 8 KB
    __shared__ ull sW3A[HH][HH / 2];     // 4 KB
    __shared__ ull sW4B[HH][HH];         // 8 KB
    __shared__ float sB2[HH], sB3[HH], sB4[DD];
    int tid = threadIdx.x;
    for (int i = tid; i < DD * (HH / 2); i += 128) ((ull*)sW2)[i] = ((ull*)dW2P)[i];
    for (int i = tid; i < HH * (HH / 2); i += 128) ((ull*)sW3A)[i] = ((ull*)dW3AP)[i];
    for (int i = tid; i < HH * HH; i += 128) ((ull*)sW4B)[i] = ((ull*)dW4BP)[i];
    if (tid < HH) { sB2[tid] = dB2[tid]; sB3[tid] = dB3[tid]; }
    if (tid < DD) sB4[tid] = dB4[tid];
    __syncthreads();

    int p = blockIdx.x * 128 + tid;
    int b = p / NN;
    int n = p - b * NN;

    ull acc[HH / 2];
#pragma unroll
    for (int hp = 0; hp < 16; hp++) acc[hp] = 0ull;
    const float* fp = feat + (size_t)b * DD * NN + n;
#pragma unroll
    for (int c = 0; c < DD; c++) {
        float x = fp[(size_t)c * NN];
        ull xd = pack2(x, x);
#pragma unroll
        for (int hp = 0; hp < 16; hp++) acc[hp] = ffma2(sW2[c][hp], xd, acc[hp]);
    }
    float f[HH];
#pragma unroll
    for (int hp = 0; hp < 16; hp++) {
        float lo, hi;
        unpack2(acc[hp], lo, hi);
        f[2 * hp] = fmaxf(lo + sB2[2 * hp], 0.0f);
        f[2 * hp + 1] = fmaxf(hi + sB2[2 * hp + 1], 0.0f);
    }

    // G = s3*(W3a @ f) + b3, stored PERMUTED for pass2 fragment loads
#pragma unroll
    for (int hp = 0; hp < 16; hp++) acc[hp] = pack2(sB3[2 * hp], sB3[2 * hp + 1]);
#pragma unroll
    for (int c = 0; c < HH; c++) {
        ull xd = pack2(f[c], f[c]);
#pragma unroll
        for (int hp = 0; hp < 16; hp++) acc[hp] = ffma2(sW3A[c][hp], xd, acc[hp]);
    }
    ull* Grow = (ull*)(dG + (size_t)p * HH);
#pragma unroll
    for (int hp = 0; hp < 16; hp++) Grow[(hp & 3) * 4 + (hp >> 2)] = acc[hp];

    // E = W4b @ f + b4 (64 outputs, two halves of 16 d-pairs)
    float* Erow = dE + (size_t)p * DD;
#pragma unroll
    for (int half = 0; half < 2; half++) {
        ull acc2[16];
#pragma unroll
        for (int dq = 0; dq < 16; dq++)
            acc2[dq] = pack2(sB4[half * 32 + 2 * dq], sB4[half * 32 + 2 * dq + 1]);
#pragma unroll
        for (int c = 0; c < HH; c++) {
            ull xd = pack2(f[c], f[c]);
            const ull* wr = &sW4B[c][half * 16];
#pragma unroll
            for (int dq = 0; dq < 16; dq++) acc2[dq] = ffma2(wr[dq], xd, acc2[dq]);
        }
#pragma unroll
        for (int dq = 0; dq < 8; dq++) {
            float a0, a1, a2, a3;
            unpack2(acc2[2 * dq], a0, a1);
            unpack2(acc2[2 * dq + 1], a2, a3);
            ((float4*)Erow)[half * 8 + dq] = make_float4(a0, a1, a2, a3);
        }
    }

    const float* xp = xyz + (size_t)p * 3;
    dXYZ4[p] = make_float4(xp[0], xp[1], xp[2], 0.0f);
}

// ================== pass 2: gather + tf32 MMA + max-pool + fused W4a epilogue ==================
// staged row (36 floats): [0:32] = permuted G of neighbor j, [32:36] = xyz4 of j
#define RS 36

__global__ void __launch_bounds__(256, 2) pass2_kernel(float* __restrict__ out) {
    __shared__ float sG[2][8][16 * RS];      // 36864 B, double-buffered stage
    __shared__ int sIdx[8][256];             // 8192 B, per-warp neighbor indices
    __shared__ float4 sCA[HH], sCB[HH];      // 1024 B
    int tid = threadIdx.x;
    if (tid < HH) { sCA[tid] = dCoefA[tid]; sCB[tid] = dCoefB[tid]; }
    {
        const int4* src = (const int4*)dIdx32buf + (size_t)blockIdx.x * 512;
        int4* dst = (int4*)sIdx;
        for (int t = tid; t < 512; t += 256) dst[t] = src[t];
    }
    __syncthreads();

    int lane = tid & 31, warp = tid >> 5;
    int gid = lane >> 2, tig = lane & 3;

    // W3b B fragments resident in registers
    u32 B[4][4][2];
#pragma unroll
    for (int s = 0; s < 4; s++)
#pragma unroll
        for (int nt = 0; nt < 4; nt++) {
            B[s][nt][0] = dW3Btf[(nt * 8 + gid) * HH + 8 * s + tig];
            B[s][nt][1] = dW3Btf[(nt * 8 + gid) * HH + 8 * s + tig + 4];
        }

    int pbase = (blockIdx.x * 8 + warp) * PPW;
    int bBase = (pbase / NN) * NN;
    const int* iw = sIdx[warp];
    float* buf0 = sG[0][warp];
    float* buf1 = sG[1][warp];

#define STAGE(I, BUF)                                                                  \
    {                                                                                  \
        _Pragma("unroll")                                                              \
        for (int u = 0; u < 5; u++) {                                                  \
            int c = u * 32 + lane;                                                     \
            if (c < 144) {                                                             \
                int row = c / 9;                                                       \
                int ch = c - row * 9;                                                  \
                int j = bBase + iw[(I) * 16 + row];                                    \
                const float* src = (ch < 8) ? (dG + (size_t)j * HH + ch * 4)           \
                                            : (const float*)(dXYZ4 + j);               \
                u32 dst = smem_u32((BUF) + row * RS + ch * 4);                         \
                asm volatile("cp.async.cg.shared.global [%0], [%1], 16;"               \
                             :: "r"(dst), "l"(src));                                   \
            }                                                                          \
        }                                                                              \
        asm volatile("cp.async.commit_group;");                                        \
    }

    STAGE(0, buf0);

#pragma unroll 1
    for (int i = 0; i < PPW; i++) {
        float* cbuf = (i & 1) ? buf1 : buf0;
        float* nbuf = (i & 1) ? buf0 : buf1;
        if (i < PPW - 1) {
            STAGE(i + 1, nbuf);
            asm volatile("cp.async.wait_group 1;");
        } else {
            asm volatile("cp.async.wait_group 0;");
        }
        __syncwarp();

        int p = pbase + i;
        float4 xc = dXYZ4[p];  // uniform per warp
        float4 xa = *(const float4*)(cbuf + gid * RS + 32);
        float4 xb = *(const float4*)(cbuf + (gid + 8) * RS + 32);

        const float4* g0p = (const float4*)(cbuf + gid * RS + tig * 8);
        const float4* g1p = (const float4*)(cbuf + (gid + 8) * RS + tig * 8);
        float4 qa0 = g0p[0], qa1 = g0p[1];
        float4 qb0 = g1p[0], qb1 = g1p[1];
        float C[4][4];
        C[0][0] = qa0.x; C[0][1] = qa0.y; C[1][0] = qa0.z; C[1][1] = qa0.w;
        C[2][0] = qa1.x; C[2][1] = qa1.y; C[3][0] = qa1.z; C[3][1] = qa1.w;
        C[0][2] = qb0.x; C[0][3] = qb0.y; C[1][2] = qb0.z; C[1][3] = qb0.w;
        C[2][2] = qb1.x; C[2][3] = qb1.y; C[3][2] = qb1.z; C[3][3] = qb1.w;

        float dxa = xc.x - xa.x, dya = xc.y - xa.y, dza = xc.z - xa.z;
        float dis0 = sqrtf(dxa * dxa + dya * dya + dza * dza);
        float dxb = xc.x - xb.x, dyb = xc.y - xb.y, dzb = xc.z - xb.z;
        float dis1 = sqrtf(dxb * dxb + dyb * dyb + dzb * dzb);

        u32 A[4][4];
#pragma unroll
        for (int t = 0; t < 8; t++) {
            float4 ca = sCA[tig + 4 * t];
            float4 cb = sCB[tig + 4 * t];
            float bb = fmaf(cb.x, xc.x, fmaf(cb.y, xc.y, fmaf(cb.z, xc.z, cb.w)));
            float v0 = fmaxf(fmaf(ca.x, xa.x, fmaf(ca.y, xa.y, fmaf(ca.z, xa.z, fmaf(ca.w, dis0, bb)))), 0.0f);
            float v1 = fmaxf(fmaf(ca.x, xb.x, fmaf(ca.y, xb.y, fmaf(ca.z, xb.z, fmaf(ca.w, dis1, bb)))), 0.0f);
            int s = t >> 1;
            if ((t & 1) == 0) { A[s][0] = cvt_tf32(v0); A[s][1] = cvt_tf32(v1); }
            else              { A[s][2] = cvt_tf32(v0); A[s][3] = cvt_tf32(v1); }
        }

#pragma unroll
        for (int s = 0; s < 4; s++)
#pragma unroll
            for (int nt = 0; nt < 4; nt++)
                mma_tf32(C[nt][0], C[nt][1], C[nt][2], C[nt][3],
                         A[s][0], A[s][1], A[s][2], A[s][3], B[s][nt][0], B[s][nt][1]);

        // max over 16 k-rows
        float r0[4], r1[4];
#pragma unroll
        for (int nt = 0; nt < 4; nt++) {
            r0[nt] = fmaxf(C[nt][0], C[nt][2]);
            r1[nt] = fmaxf(C[nt][1], C[nt][3]);
        }
#pragma unroll
        for (int off = 4; off <= 16; off <<= 1)
#pragma unroll
            for (int nt = 0; nt < 4; nt++) {
                r0[nt] = fmaxf(r0[nt], __shfl_xor_sync(0xffffffffu, r0[nt], off));
                r1[nt] = fmaxf(r1[nt], __shfl_xor_sync(0xffffffffu, r1[nt], off));
            }
        if (gid == 0) {
#pragma unroll
            for (int nt = 0; nt < 4; nt++) {
                float2 v = make_float2(fmaxf(r0[nt], 0.0f), fmaxf(r1[nt], 0.0f));
                *(float2*)(dFC + (size_t)p * HH + nt * 8 + 2 * tig) = v;
            }
        }
    }
#undef STAGE

    // ---- fused epilogue: out = relu(W4a @ fc + E) for this warp's 16 points ----
    __syncwarp();  // fc writes (warp-private) visible
    u32 Af[4][4];
    const float* fcb = dFC + (size_t)pbase * HH;
#pragma unroll
    for (int s = 0; s < 4; s++) {
        Af[s][0] = cvt_tf32(fcb[gid * HH + 8 * s + tig]);
        Af[s][1] = cvt_tf32(fcb[(gid + 8) * HH + 8 * s + tig]);
        Af[s][2] = cvt_tf32(fcb[gid * HH + 8 * s + tig + 4]);
        Af[s][3] = cvt_tf32(fcb[(gid + 8) * HH + 8 * s + tig + 4]);
    }
    int bOut = pbase / NN;
    float* outB = out + (size_t)bOut * DD * NN;
    int n0 = pbase - bOut * NN;
#pragma unroll
    for (int nt = 0; nt < 8; nt++) {
        float2 e0 = *(const float2*)(dE + (size_t)(pbase + gid) * DD + nt * 8 + 2 * tig);
        float2 e1 = *(const float2*)(dE + (size_t)(pbase + gid + 8) * DD + nt * 8 + 2 * tig);
        float c0 = e0.x, c1 = e0.y, c2 = e1.x, c3 = e1.y;
#pragma unroll
        for (int s = 0; s < 4; s++) {
            u32 b0 = dW4Atf[(nt * 8 + gid) * HH + 8 * s + tig];
            u32 b1 = dW4Atf[(nt * 8 + gid) * HH + 8 * s + tig + 4];
            mma_tf32(c0, c1, c2, c3, Af[s][0], Af[s][1], Af[s][2], Af[s][3], b0, b1);
        }
        int d0 = nt * 8 + 2 * tig;
        outB[(size_t)d0 * NN + n0 + gid] = fmaxf(c0, 0.0f);
        outB[(size_t)(d0 + 1) * NN + n0 + gid] = fmaxf(c1, 0.0f);
        outB[(size_t)d0 * NN + n0 + gid + 8] = fmaxf(c2, 0.0f);
        outB[(size_t)(d0 + 1) * NN + n0 + gid + 8] = fmaxf(c3, 0.0f);
    }
}

// ================== launch ==================
extern "C" void kernel_launch(void* const* d_in, const int* in_sizes, int n_in,
                              void* d_out, int out_size) {
    const float *feat, *xyz, *W1, *W2, *W3, *W4;
    const float *g1, *b1, *g2, *b2, *g3, *b3, *g4, *b4;
    const void* idx;
    if (n_in >= 3 && in_sizes[2] == 320) {
        feat = (const float*)d_in[0];  xyz = (const float*)d_in[1];
        W1 = (const float*)d_in[2];    g1 = (const float*)d_in[3];  b1 = (const float*)d_in[4];
        W2 = (const float*)d_in[5];    g2 = (const float*)d_in[6];  b2 = (const float*)d_in[7];
        W3 = (const float*)d_in[8];    g3 = (const float*)d_in[9];  b3 = (const float*)d_in[10];
        W4 = (const float*)d_in[11];   g4 = (const float*)d_in[12]; b4 = (const float*)d_in[13];
        idx = d_in[14];
    } else {
        feat = (const float*)d_in[0];  xyz = (const float*)d_in[1];  idx = d_in[2];
        W1 = (const float*)d_in[3];    W2 = (const float*)d_in[4];
        W3 = (const float*)d_in[5];    W4 = (const float*)d_in[6];
        g1 = (const float*)d_in[7];    b1 = (const float*)d_in[8];
        g2 = (const float*)d_in[9];    b2 = (const float*)d_in[10];
        g3 = (const float*)d_in[11];   b3 = (const float*)d_in[12];
        g4 = (const float*)d_in[13];   b4 = (const float*)d_in[14];
    }
    prep_kernel<<<1, 256>>>(W1, W2, W3, W4, g1, b1, g2, b2, g3, b3, g4, b4);
    detect_kernel<<<1, 256>>>((const unsigned int*)idx);
    convert_kernel<<<NPTS * KK / 256, 256>>>((const unsigned int*)idx);
    pass1_kernel<<<NPTS / 128, 128>>>(feat, xyz);
    pass2_kernel<<<NPTS / (8 * PPW), 256>>>((float*)d_out);
}